// round 5
// baseline (speedup 1.0000x reference)
#include <cuda_runtime.h>

#define NQ   9
#define DIM  512
#define NL   10
#define BATCH 16384
#define NCLS 10

// ---------------- static scratch (no allocs allowed) ----------------
__device__ float2 g_rot[NL * NQ * 4];     // u00,u01,u10,u11 per Rot gate
__device__ float2 g_crx[NL * NQ];         // (cos(t/2), sin(t/2)) per CRX gate
__device__ float2 g_UT[DIM * DIM];        // g_UT[j][i] = (U e_j)_i   (2 MB)
__device__ float2 g_Y[(size_t)BATCH * DIM]; // Y = X * U^T             (64 MB)

// ---------------- packed f32x2 helpers ----------------
__device__ __forceinline__ unsigned long long pk2(float x) {
    unsigned long long r;
    unsigned u = __float_as_uint(x);
    asm("mov.b64 %0, {%1, %2};" : "=l"(r) : "r"(u), "r"(u));
    return r;
}
__device__ __forceinline__ void cfma(unsigned long long& acc,
                                     unsigned long long a,
                                     unsigned long long b) {
    asm("fma.rn.f32x2 %0, %1, %2, %0;" : "+l"(acc) : "l"(a), "l"(b));
}

// ---------------- kernel 0: gate matrices ----------------
__global__ void gate_prep(const float* __restrict__ rot,
                          const float* __restrict__ crx) {
    int idx = threadIdx.x;
    if (idx >= NL * NQ) return;
    float phi = rot[idx * 3 + 0], theta = rot[idx * 3 + 1], omega = rot[idx * 3 + 2];
    float s, c;  sincosf(0.5f * theta, &s, &c);
    float a = 0.5f * (phi + omega), b = 0.5f * (phi - omega);
    float sa, ca; sincosf(a, &sa, &ca);
    float sb, cb; sincosf(b, &sb, &cb);
    // PennyLane Rot = [[e^{-ia}c, -e^{ib}s],[e^{-ib}s, e^{ia}c]]
    g_rot[idx * 4 + 0] = make_float2( ca * c, -sa * c);
    g_rot[idx * 4 + 1] = make_float2(-cb * s, -sb * s);
    g_rot[idx * 4 + 2] = make_float2( cb * s, -sb * s);
    g_rot[idx * 4 + 3] = make_float2( ca * c,  sa * c);
    float t = crx[idx];
    float st, ct; sincosf(0.5f * t, &st, &ct);
    g_crx[idx] = make_float2(ct, st);
}

// ---------------- kernel 1: build U (one block per basis column) ----------------
// qubit q  <->  bit (8 - q)  (reference reshape is MSB-first)
__global__ __launch_bounds__(256) void build_u() {
    __shared__ float2 psi[DIM];
    int col = blockIdx.x, tid = threadIdx.x;
    psi[tid]       = make_float2(tid == col ? 1.f : 0.f, 0.f);
    psi[tid + 256] = make_float2((tid + 256) == col ? 1.f : 0.f, 0.f);

    for (int n = 0; n < NL; n++) {
        // 9 single-qubit Rot gates
        for (int i = 0; i < NQ; i++) {
            int g = n * NQ + i;
            float2 u00 = g_rot[g * 4 + 0], u01 = g_rot[g * 4 + 1];
            float2 u10 = g_rot[g * 4 + 2], u11 = g_rot[g * 4 + 3];
            int k = 8 - i;
            __syncthreads();
            int p  = tid;
            int i0 = ((p >> k) << (k + 1)) | (p & ((1 << k) - 1));
            int i1 = i0 | (1 << k);
            float2 av = psi[i0], bv = psi[i1];
            psi[i0] = make_float2(
                u00.x * av.x - u00.y * av.y + u01.x * bv.x - u01.y * bv.y,
                u00.x * av.y + u00.y * av.x + u01.x * bv.y + u01.y * bv.x);
            psi[i1] = make_float2(
                u10.x * av.x - u10.y * av.y + u11.x * bv.x - u11.y * bv.y,
                u10.x * av.y + u10.y * av.x + u11.x * bv.y + u11.y * bv.x);
        }
        // 9 CRX gates: control qubit i (bit 8-i), target (i+1)%9 (bit 8-((i+1)%9))
        for (int i = 0; i < NQ; i++) {
            int g = n * NQ + i;
            float2 cs = g_crx[g];
            int kc = 8 - i, kt = 8 - ((i + 1) % NQ);
            int lo = kc < kt ? kc : kt;
            int hi = kc < kt ? kt : kc;
            __syncthreads();
            if (tid < 128) {
                int x = tid;
                x = ((x >> lo) << (lo + 1)) | (x & ((1 << lo) - 1));
                x = ((x >> hi) << (hi + 1)) | (x & ((1 << hi) - 1));
                int i0 = x | (1 << kc);        // control=1, target=0
                int i1 = i0 | (1 << kt);       // control=1, target=1
                float2 av = psi[i0], bv = psi[i1];
                // [[c, -is],[-is, c]]
                psi[i0] = make_float2(cs.x * av.x + cs.y * bv.y,
                                      cs.x * av.y - cs.y * bv.x);
                psi[i1] = make_float2(cs.x * bv.x + cs.y * av.y,
                                      cs.x * bv.y - cs.y * av.x);
            }
        }
    }
    __syncthreads();
    g_UT[col * DIM + tid]       = psi[tid];
    g_UT[col * DIM + tid + 256] = psi[tid + 256];
}

// ---------------- kernel 2: Y = X * UT  (real X, complex UT) ----------------
// BM=64 rows, BN=64 complex cols, BK=16, 256 threads, 4x4 complex per thread.
__global__ __launch_bounds__(256) void gemm_k(const float* __restrict__ X) {
    __shared__ float  As[16][68];   // As[k][m], padded
    __shared__ float2 Bs[16][64];   // Bs[k][n]

    int tid  = threadIdx.x;
    int row0 = blockIdx.y * 64;
    int col0 = blockIdx.x * 64;
    int m0 = (tid >> 4) << 2;       // (tid/16)*4
    int n0 = (tid & 15) << 2;       // (tid%16)*4

    unsigned long long acc[4][4];
#pragma unroll
    for (int i = 0; i < 4; i++)
#pragma unroll
        for (int j = 0; j < 4; j++) acc[i][j] = 0ULL;

    int am = tid >> 2;              // 0..63
    int ak = (tid & 3) << 2;        // 0,4,8,12
    const float* Xp = X + (size_t)(row0 + am) * DIM + ak;
    int bk = tid >> 5;              // 0..7
    int bn = (tid & 31) * 2;        // even float2 col

#pragma unroll 1
    for (int k0 = 0; k0 < DIM; k0 += 16) {
        float4 av  = *(const float4*)(Xp + k0);
        float4 bv0 = *(const float4*)&g_UT[(k0 + bk)     * DIM + col0 + bn];
        float4 bv1 = *(const float4*)&g_UT[(k0 + 8 + bk) * DIM + col0 + bn];
        __syncthreads();
        As[ak + 0][am] = av.x; As[ak + 1][am] = av.y;
        As[ak + 2][am] = av.z; As[ak + 3][am] = av.w;
        *(float4*)&Bs[bk][bn]     = bv0;
        *(float4*)&Bs[bk + 8][bn] = bv1;
        __syncthreads();
#pragma unroll
        for (int kk = 0; kk < 16; kk++) {
            float4 a = *(const float4*)&As[kk][m0];
            ulonglong2 b01 = *(const ulonglong2*)&Bs[kk][n0];
            ulonglong2 b23 = *(const ulonglong2*)&Bs[kk][n0 + 2];
            unsigned long long a0 = pk2(a.x), a1 = pk2(a.y),
                               a2 = pk2(a.z), a3 = pk2(a.w);
            cfma(acc[0][0], a0, b01.x); cfma(acc[0][1], a0, b01.y);
            cfma(acc[0][2], a0, b23.x); cfma(acc[0][3], a0, b23.y);
            cfma(acc[1][0], a1, b01.x); cfma(acc[1][1], a1, b01.y);
            cfma(acc[1][2], a1, b23.x); cfma(acc[1][3], a1, b23.y);
            cfma(acc[2][0], a2, b01.x); cfma(acc[2][1], a2, b01.y);
            cfma(acc[2][2], a2, b23.x); cfma(acc[2][3], a2, b23.y);
            cfma(acc[3][0], a3, b01.x); cfma(acc[3][1], a3, b01.y);
            cfma(acc[3][2], a3, b23.x); cfma(acc[3][3], a3, b23.y);
        }
    }
#pragma unroll
    for (int i = 0; i < 4; i++) {
        float2* yr = g_Y + (size_t)(row0 + m0 + i) * DIM + col0 + n0;
        ulonglong2 v;
        v.x = acc[i][0]; v.y = acc[i][1]; *(ulonglong2*)yr       = v;
        v.x = acc[i][2]; v.y = acc[i][3]; *(ulonglong2*)(yr + 2) = v;
    }
}

// ---------------- kernel 3: probs -> <Z> -> linear head -> log_softmax ----------------
__global__ __launch_bounds__(256) void reduce_k(const float* __restrict__ fc_w,
                                                const float* __restrict__ fc_b,
                                                float* __restrict__ out) {
    int gw   = (blockIdx.x * blockDim.x + threadIdx.x) >> 5;  // row
    int lane = threadIdx.x & 31;
    const float2* yr = g_Y + (size_t)gw * DIM;

    float acc[10];
#pragma unroll
    for (int q = 0; q < 10; q++) acc[q] = 0.f;

#pragma unroll
    for (int t = 0; t < 16; t++) {
        int i = lane + (t << 5);
        float2 v = yr[i];
        float p = v.x * v.x + v.y * v.y;
        acc[9] += p;
#pragma unroll
        for (int q = 0; q < 9; q++)
            acc[q] += ((i >> (8 - q)) & 1) ? -p : p;
    }
#pragma unroll
    for (int o = 16; o; o >>= 1)
#pragma unroll
        for (int q = 0; q < 10; q++)
            acc[q] += __shfl_xor_sync(0xffffffffu, acc[q], o);

    if (lane == 0) {
        float inv = 1.0f / acc[9];   // replaces input normalization (scale-invariant)
        float z[9];
#pragma unroll
        for (int q = 0; q < 9; q++) z[q] = acc[q] * inv;
        float lg[10]; float mx = -1e30f;
#pragma unroll
        for (int c = 0; c < NCLS; c++) {
            float s = fc_b[c];
#pragma unroll
            for (int q = 0; q < 9; q++) s = fmaf(fc_w[c * 9 + q], z[q], s);
            lg[c] = s; mx = fmaxf(mx, s);
        }
        float se = 0.f;
#pragma unroll
        for (int c = 0; c < NCLS; c++) se += expf(lg[c] - mx);
        float lse = mx + logf(se);
        float* o10 = out + (size_t)gw * NCLS;
#pragma unroll
        for (int c = 0; c < NCLS; c++) o10[c] = lg[c] - lse;
    }
}

// ---------------- launch ----------------
extern "C" void kernel_launch(void* const* d_in, const int* in_sizes, int n_in,
                              void* d_out, int out_size) {
    const float* x    = (const float*)d_in[0];
    const float* rot  = (const float*)d_in[1];
    const float* crx  = (const float*)d_in[2];
    const float* fc_w = (const float*)d_in[3];
    const float* fc_b = (const float*)d_in[4];
    float* out = (float*)d_out;

    gate_prep<<<1, 128>>>(rot, crx);
    build_u<<<DIM, 256>>>();
    dim3 gg(DIM / 64, BATCH / 64);
    gemm_k<<<gg, 256>>>(x);
    reduce_k<<<BATCH / 8, 256>>>(fc_w, fc_b, out);
    (void)in_sizes; (void)n_in; (void)out_size;
}

// round 8
// speedup vs baseline: 2.6940x; 2.6940x over previous
#include <cuda_runtime.h>
#include <cstdint>

#define NQ    9
#define DIM   512
#define NL    10
#define BATCH 16384
#define NCLS  10

#define BM 128
#define BN 128              // real columns per CTA
#define BKC 32              // K chunk
#define NCHUNK (DIM / BKC)
#define ASTRIDE 36          // padded row stride (floats)

// ---------------- static scratch ----------------
__device__ float2 g_rot[NL * NQ * 4];
__device__ float2 g_crx[NL * NQ];
__device__ float2 g_UT[DIM * DIM];              // [k][c] complex  (2 MB)
__device__ float  g_Bt[1024 * DIM];             // B^T [n][k] real, tf32-rounded (2 MB)
__device__ float  g_Xt[(size_t)BATCH * DIM];    // X tf32-rounded (33.5 MB)
__device__ float  g_part[8 * (size_t)BATCH * 10];   // 5.2 MB

// ---------------- helpers ----------------
__device__ __forceinline__ uint32_t smem_u32(const void* p) {
    uint32_t a;
    asm("{ .reg .u64 t; cvta.to.shared.u64 t, %1; cvt.u32.u64 %0, t; }" : "=r"(a) : "l"(p));
    return a;
}
__device__ __forceinline__ void cp16(uint32_t dst, const void* src) {
    asm volatile("cp.async.cg.shared.global [%0], [%1], 16;" :: "r"(dst), "l"(src));
}
__device__ __forceinline__ uint32_t f2tf32(float f) {
    uint32_t u;
    asm("cvt.rna.tf32.f32 %0, %1;" : "=r"(u) : "f"(f));
    return u;
}
__device__ __forceinline__ void mma_tf32(float* d,
                                         uint32_t a0, uint32_t a1, uint32_t a2, uint32_t a3,
                                         uint32_t b0, uint32_t b1) {
    asm volatile("mma.sync.aligned.m16n8k8.row.col.f32.tf32.tf32.f32 "
                 "{%0,%1,%2,%3}, {%4,%5,%6,%7}, {%8,%9}, {%0,%1,%2,%3};"
                 : "+f"(d[0]), "+f"(d[1]), "+f"(d[2]), "+f"(d[3])
                 : "r"(a0), "r"(a1), "r"(a2), "r"(a3), "r"(b0), "r"(b1));
}

// ---------------- kernel 0: gate matrices ----------------
__global__ void gate_prep(const float* __restrict__ rot,
                          const float* __restrict__ crx) {
    int idx = threadIdx.x;
    if (idx >= NL * NQ) return;
    float phi = rot[idx * 3 + 0], theta = rot[idx * 3 + 1], omega = rot[idx * 3 + 2];
    float s, c;  sincosf(0.5f * theta, &s, &c);
    float a = 0.5f * (phi + omega), b = 0.5f * (phi - omega);
    float sa, ca; sincosf(a, &sa, &ca);
    float sb, cb; sincosf(b, &sb, &cb);
    g_rot[idx * 4 + 0] = make_float2( ca * c, -sa * c);
    g_rot[idx * 4 + 1] = make_float2(-cb * s, -sb * s);
    g_rot[idx * 4 + 2] = make_float2( cb * s, -sb * s);
    g_rot[idx * 4 + 3] = make_float2( ca * c,  sa * c);
    float t = crx[idx];
    float st, ct; sincosf(0.5f * t, &st, &ct);
    g_crx[idx] = make_float2(ct, st);
}

// ---------------- kernel 1: build U (validated in R5) ----------------
__global__ __launch_bounds__(256) void build_u() {
    __shared__ float2 psi[DIM];
    int col = blockIdx.x, tid = threadIdx.x;
    psi[tid]       = make_float2(tid == col ? 1.f : 0.f, 0.f);
    psi[tid + 256] = make_float2((tid + 256) == col ? 1.f : 0.f, 0.f);

    for (int n = 0; n < NL; n++) {
        for (int i = 0; i < NQ; i++) {
            int g = n * NQ + i;
            float2 u00 = g_rot[g * 4 + 0], u01 = g_rot[g * 4 + 1];
            float2 u10 = g_rot[g * 4 + 2], u11 = g_rot[g * 4 + 3];
            int k = 8 - i;
            __syncthreads();
            int p  = tid;
            int i0 = ((p >> k) << (k + 1)) | (p & ((1 << k) - 1));
            int i1 = i0 | (1 << k);
            float2 av = psi[i0], bv = psi[i1];
            psi[i0] = make_float2(
                u00.x * av.x - u00.y * av.y + u01.x * bv.x - u01.y * bv.y,
                u00.x * av.y + u00.y * av.x + u01.x * bv.y + u01.y * bv.x);
            psi[i1] = make_float2(
                u10.x * av.x - u10.y * av.y + u11.x * bv.x - u11.y * bv.y,
                u10.x * av.y + u10.y * av.x + u11.x * bv.y + u11.y * bv.x);
        }
        for (int i = 0; i < NQ; i++) {
            int g = n * NQ + i;
            float2 cs = g_crx[g];
            int kc = 8 - i, kt = 8 - ((i + 1) % NQ);
            int lo = kc < kt ? kc : kt;
            int hi = kc < kt ? kt : kc;
            __syncthreads();
            if (tid < 128) {
                int x = tid;
                x = ((x >> lo) << (lo + 1)) | (x & ((1 << lo) - 1));
                x = ((x >> hi) << (hi + 1)) | (x & ((1 << hi) - 1));
                int i0 = x | (1 << kc);
                int i1 = i0 | (1 << kt);
                float2 av = psi[i0], bv = psi[i1];
                psi[i0] = make_float2(cs.x * av.x + cs.y * bv.y,
                                      cs.x * av.y - cs.y * bv.x);
                psi[i1] = make_float2(cs.x * bv.x + cs.y * av.y,
                                      cs.x * bv.y - cs.y * av.x);
            }
        }
    }
    __syncthreads();
    g_UT[col * DIM + tid]       = psi[tid];
    g_UT[col * DIM + tid + 256] = psi[tid + 256];
}

// ---------------- kernel 2a: transpose real view of U, round to tf32 ----------------
__global__ __launch_bounds__(256) void conv_b() {
    __shared__ float tile[32][33];
    int n0 = blockIdx.x * 32;
    int k0 = blockIdx.y * 32;
    int tx = threadIdx.x & 31, ty = threadIdx.x >> 5;
    const float* Br = (const float*)g_UT;      // Br[k][n], n<1024
#pragma unroll
    for (int j = 0; j < 32; j += 8)
        tile[ty + j][tx] = Br[(size_t)(k0 + ty + j) * 1024 + n0 + tx];
    __syncthreads();
#pragma unroll
    for (int j = 0; j < 32; j += 8) {
        uint32_t r = f2tf32(tile[tx][ty + j]);
        g_Bt[(size_t)(n0 + ty + j) * 512 + k0 + tx] = __uint_as_float(r);
    }
}

// ---------------- kernel 2b: round X to tf32 ----------------
__global__ __launch_bounds__(256) void conv_x(const float* __restrict__ X) {
    size_t idx = (size_t)(blockIdx.x * 256 + threadIdx.x);
    float4 v = ((const float4*)X)[idx];
    float4 o;
    o.x = __uint_as_float(f2tf32(v.x));
    o.y = __uint_as_float(f2tf32(v.y));
    o.z = __uint_as_float(f2tf32(v.z));
    o.w = __uint_as_float(f2tf32(v.w));
    ((float4*)g_Xt)[idx] = o;
}

// ---------------- kernel 3: tf32 HMMA GEMM + fused <Z> epilogue ----------------
// smem floats: A0 [0,4608) B0 [4608,9216) A1 [9216,13824) B1 [13824,18432)
#define SMEM_FLOATS 18432
#define SMEM_BYTES  (SMEM_FLOATS * 4)

__global__ __launch_bounds__(256, 2) void gemm_tc() {
    extern __shared__ float smem[];
    uint32_t sb = smem_u32(smem);
    int tid = threadIdx.x, wid = tid >> 5, lane = tid & 31;
    int bx = blockIdx.x;            // n tile (8)
    int m0 = blockIdx.y * BM;
    int n0 = bx * BN;

    int mw = (wid & 1) * 64;        // warp M offset
    int nw = (wid >> 1) * 32;       // warp N offset (real)
    int r  = lane >> 2, cg = lane & 3;

    float acc[4][4][4];
#pragma unroll
    for (int i = 0; i < 4; i++)
#pragma unroll
        for (int j = 0; j < 4; j++)
#pragma unroll
            for (int v = 0; v < 4; v++) acc[i][j][v] = 0.f;

    int row = tid >> 1;             // 0..127
    int off = (tid & 1) * 16;       // float offset in 32-float chunk row

    const float* ApB = g_Xt + (size_t)(m0 + row) * DIM + off;
    const float* BpB = g_Bt + (size_t)(n0 + row) * DIM + off;

    // prefetch chunk 0 (full 64B per thread per tile)
    {
        uint32_t da = sb + (uint32_t)(row * ASTRIDE + off) * 4u;
        uint32_t db = da + 4608u * 4u;
#pragma unroll
        for (int s = 0; s < 4; s++) {
            cp16(da + s * 16, ApB + s * 4);
            cp16(db + s * 16, BpB + s * 4);
        }
    }
    asm volatile("cp.async.commit_group;");

    for (int ki = 0; ki < NCHUNK; ki++) {
        if (ki + 1 < NCHUNK) {
            int kb = (ki + 1) * BKC;
            uint32_t bufo = ((ki + 1) & 1) * 9216u * 4u;
            uint32_t da = sb + bufo + (uint32_t)(row * ASTRIDE + off) * 4u;
            uint32_t db = da + 4608u * 4u;
#pragma unroll
            for (int s = 0; s < 4; s++) {
                cp16(da + s * 16, ApB + kb + s * 4);
                cp16(db + s * 16, BpB + kb + s * 4);
            }
            asm volatile("cp.async.commit_group;");
            asm volatile("cp.async.wait_group 1;");
        } else {
            asm volatile("cp.async.wait_group 0;");
        }
        __syncthreads();

        const float* As = smem + (ki & 1) * 9216;
        const float* Bs = As + 4608;
#pragma unroll
        for (int ks = 0; ks < 4; ks++) {
            uint32_t a[4][4], b[4][2];
#pragma unroll
            for (int i = 0; i < 4; i++) {
                const float* ap = As + (mw + 16 * i + r) * ASTRIDE + ks * 8 + cg;
                a[i][0] = __float_as_uint(ap[0]);
                a[i][1] = __float_as_uint(ap[8 * ASTRIDE]);
                a[i][2] = __float_as_uint(ap[4]);
                a[i][3] = __float_as_uint(ap[8 * ASTRIDE + 4]);
            }
#pragma unroll
            for (int j = 0; j < 4; j++) {
                const float* bp = Bs + (nw + 8 * j + r) * ASTRIDE + ks * 8 + cg;
                b[j][0] = __float_as_uint(bp[0]);
                b[j][1] = __float_as_uint(bp[4]);
            }
#pragma unroll
            for (int i = 0; i < 4; i++)
#pragma unroll
                for (int j = 0; j < 4; j++)
                    mma_tf32(acc[i][j], a[i][0], a[i][1], a[i][2], a[i][3],
                             b[j][0], b[j][1]);
        }
        __syncthreads();
    }

    // ---- fused epilogue: |y|^2 -> signed partials over this CTA's 64 complex cols ----
    float* part = smem;             // reuse: [128][10]
    for (int t = tid; t < 1280; t += 256) part[t] = 0.f;
    __syncthreads();

#pragma unroll
    for (int i = 0; i < 4; i++) {
#pragma unroll
        for (int v = 0; v < 2; v++) {
            int prow = mw + 16 * i + r + 8 * v;
            float loc[10];
#pragma unroll
            for (int q = 0; q < 10; q++) loc[q] = 0.f;
#pragma unroll
            for (int j = 0; j < 4; j++) {
                float re = acc[i][j][2 * v], im = acc[i][j][2 * v + 1];
                float p = fmaf(re, re, im * im);
                int nc = bx * 64 + ((nw + 8 * j) >> 1) + cg;
                loc[9] += p;
#pragma unroll
                for (int q = 0; q < 9; q++)
                    loc[q] += ((nc >> (8 - q)) & 1) ? -p : p;
            }
#pragma unroll
            for (int o = 1; o < 4; o <<= 1)
#pragma unroll
                for (int q = 0; q < 10; q++)
                    loc[q] += __shfl_xor_sync(0xffffffffu, loc[q], o);
            if (cg == 0)
#pragma unroll
                for (int q = 0; q < 10; q++)
                    atomicAdd(&part[prow * 10 + q], loc[q]);
        }
    }
    __syncthreads();
    if (tid < 128) {
        float* dst = g_part + ((size_t)bx * BATCH + m0 + tid) * 10;
#pragma unroll
        for (int q = 0; q < 10; q++) dst[q] = part[tid * 10 + q];
    }
}

// ---------------- kernel 4: sum partials -> head -> log_softmax ----------------
__global__ __launch_bounds__(256) void head_k(const float* __restrict__ fc_w,
                                              const float* __restrict__ fc_b,
                                              float* __restrict__ out) {
    int row = blockIdx.x * 256 + threadIdx.x;
    float a[10];
#pragma unroll
    for (int q = 0; q < 10; q++) a[q] = 0.f;
#pragma unroll
    for (int b = 0; b < 8; b++) {
        const float* p = g_part + ((size_t)b * BATCH + row) * 10;
#pragma unroll
        for (int q = 0; q < 10; q++) a[q] += p[q];
    }
    float inv = 1.0f / a[9];
    float z[9];
#pragma unroll
    for (int q = 0; q < 9; q++) z[q] = a[q] * inv;
    float lg[NCLS]; float mx = -1e30f;
#pragma unroll
    for (int c = 0; c < NCLS; c++) {
        float s = fc_b[c];
#pragma unroll
        for (int q = 0; q < 9; q++) s = fmaf(fc_w[c * 9 + q], z[q], s);
        lg[c] = s; mx = fmaxf(mx, s);
    }
    float se = 0.f;
#pragma unroll
    for (int c = 0; c < NCLS; c++) se += expf(lg[c] - mx);
    float lse = mx + logf(se);
    float* o10 = out + (size_t)row * NCLS;
#pragma unroll
    for (int c = 0; c < NCLS; c++) o10[c] = lg[c] - lse;
}

// ---------------- launch ----------------
extern "C" void kernel_launch(void* const* d_in, const int* in_sizes, int n_in,
                              void* d_out, int out_size) {
    const float* x    = (const float*)d_in[0];
    const float* rot  = (const float*)d_in[1];
    const float* crx  = (const float*)d_in[2];
    const float* fc_w = (const float*)d_in[3];
    const float* fc_b = (const float*)d_in[4];
    float* out = (float*)d_out;

    static bool attr_set = false;
    if (!attr_set) {
        cudaFuncSetAttribute(gemm_tc, cudaFuncAttributeMaxDynamicSharedMemorySize,
                             SMEM_BYTES);
        attr_set = true;
    }

    gate_prep<<<1, 128>>>(rot, crx);
    build_u<<<DIM, 256>>>();
    conv_b<<<dim3(32, 16), 256>>>();
    conv_x<<<(BATCH * DIM / 4) / 256, 256>>>(x);
    gemm_tc<<<dim3(1024 / BN, BATCH / BM), 256, SMEM_BYTES>>>();
    head_k<<<BATCH / 256, 256>>>(fc_w, fc_b, out);
    (void)in_sizes; (void)n_in; (void)out_size;
}

// round 9
// speedup vs baseline: 3.5544x; 1.3194x over previous
#include <cuda_runtime.h>
#include <cstdint>

#define NQ    9
#define DIM   512
#define NL    10
#define BATCH 16384
#define NCLS  10

#define BM 128
#define BN 128              // real columns per CTA
#define BKC 32              // K chunk
#define NCHUNK (DIM / BKC)

// ---------------- static scratch ----------------
__device__ float2 g_rot[NL * NQ * 4];
__device__ float2 g_crx[NL * NQ];
__device__ float2 g_UT[DIM * DIM];              // [k][c] complex  (2 MB)
__device__ float  g_Bt[1024 * DIM];             // B frag-major, tf32 (2 MB)
__device__ float  g_Xt[(size_t)BATCH * DIM];    // X frag-major, tf32 (33.5 MB)
__device__ float  g_part[8 * (size_t)BATCH * 10];   // 5.2 MB

// ---------------- helpers ----------------
__device__ __forceinline__ uint32_t smem_u32(const void* p) {
    uint32_t a;
    asm("{ .reg .u64 t; cvta.to.shared.u64 t, %1; cvt.u32.u64 %0, t; }" : "=r"(a) : "l"(p));
    return a;
}
__device__ __forceinline__ void cp16(uint32_t dst, const void* src) {
    asm volatile("cp.async.cg.shared.global [%0], [%1], 16;" :: "r"(dst), "l"(src));
}
__device__ __forceinline__ uint32_t f2tf32(float f) {
    uint32_t u;
    asm("cvt.rna.tf32.f32 %0, %1;" : "=r"(u) : "f"(f));
    return u;
}
__device__ __forceinline__ void mma_tf32(float* d,
                                         uint32_t a0, uint32_t a1, uint32_t a2, uint32_t a3,
                                         uint32_t b0, uint32_t b1) {
    asm volatile("mma.sync.aligned.m16n8k8.row.col.f32.tf32.tf32.f32 "
                 "{%0,%1,%2,%3}, {%4,%5,%6,%7}, {%8,%9}, {%0,%1,%2,%3};"
                 : "+f"(d[0]), "+f"(d[1]), "+f"(d[2]), "+f"(d[3])
                 : "r"(a0), "r"(a1), "r"(a2), "r"(a3), "r"(b0), "r"(b1));
}

// ---------------- kernel 0: gate matrices ----------------
__global__ void gate_prep(const float* __restrict__ rot,
                          const float* __restrict__ crx) {
    int idx = threadIdx.x;
    if (idx >= NL * NQ) return;
    float phi = rot[idx * 3 + 0], theta = rot[idx * 3 + 1], omega = rot[idx * 3 + 2];
    float s, c;  sincosf(0.5f * theta, &s, &c);
    float a = 0.5f * (phi + omega), b = 0.5f * (phi - omega);
    float sa, ca; sincosf(a, &sa, &ca);
    float sb, cb; sincosf(b, &sb, &cb);
    g_rot[idx * 4 + 0] = make_float2( ca * c, -sa * c);
    g_rot[idx * 4 + 1] = make_float2(-cb * s, -sb * s);
    g_rot[idx * 4 + 2] = make_float2( cb * s, -sb * s);
    g_rot[idx * 4 + 3] = make_float2( ca * c,  sa * c);
    float t = crx[idx];
    float st, ct; sincosf(0.5f * t, &st, &ct);
    g_crx[idx] = make_float2(ct, st);
}

// ---------------- kernel 1: build U (validated) ----------------
__global__ __launch_bounds__(256) void build_u() {
    __shared__ float2 psi[DIM];
    int col = blockIdx.x, tid = threadIdx.x;
    psi[tid]       = make_float2(tid == col ? 1.f : 0.f, 0.f);
    psi[tid + 256] = make_float2((tid + 256) == col ? 1.f : 0.f, 0.f);

    for (int n = 0; n < NL; n++) {
        for (int i = 0; i < NQ; i++) {
            int g = n * NQ + i;
            float2 u00 = g_rot[g * 4 + 0], u01 = g_rot[g * 4 + 1];
            float2 u10 = g_rot[g * 4 + 2], u11 = g_rot[g * 4 + 3];
            int k = 8 - i;
            __syncthreads();
            int p  = tid;
            int i0 = ((p >> k) << (k + 1)) | (p & ((1 << k) - 1));
            int i1 = i0 | (1 << k);
            float2 av = psi[i0], bv = psi[i1];
            psi[i0] = make_float2(
                u00.x * av.x - u00.y * av.y + u01.x * bv.x - u01.y * bv.y,
                u00.x * av.y + u00.y * av.x + u01.x * bv.y + u01.y * bv.x);
            psi[i1] = make_float2(
                u10.x * av.x - u10.y * av.y + u11.x * bv.x - u11.y * bv.y,
                u10.x * av.y + u10.y * av.x + u11.x * bv.y + u11.y * bv.x);
        }
        for (int i = 0; i < NQ; i++) {
            int g = n * NQ + i;
            float2 cs = g_crx[g];
            int kc = 8 - i, kt = 8 - ((i + 1) % NQ);
            int lo = kc < kt ? kc : kt;
            int hi = kc < kt ? kt : kc;
            __syncthreads();
            if (tid < 128) {
                int x = tid;
                x = ((x >> lo) << (lo + 1)) | (x & ((1 << lo) - 1));
                x = ((x >> hi) << (hi + 1)) | (x & ((1 << hi) - 1));
                int i0 = x | (1 << kc);
                int i1 = i0 | (1 << kt);
                float2 av = psi[i0], bv = psi[i1];
                psi[i0] = make_float2(cs.x * av.x + cs.y * bv.y,
                                      cs.x * av.y - cs.y * bv.x);
                psi[i1] = make_float2(cs.x * bv.x + cs.y * av.y,
                                      cs.x * bv.y - cs.y * av.x);
            }
        }
    }
    __syncthreads();
    g_UT[col * DIM + tid]       = psi[tid];
    g_UT[col * DIM + tid + 256] = psi[tid + 256];
}

// ---------------- kernel 2a: B -> fragment-major tf32 ----------------
// Bt[n][k] = Br[k][n] with Br = real view of g_UT ([k][1024]).
// Frag float4 at [np][ks][lane] = {Bt[np*16+r][8ks+cg], Bt[np*16+r][8ks+cg+4],
//                                  Bt[np*16+8+r][8ks+cg], Bt[np*16+8+r][8ks+cg+4]}
__global__ __launch_bounds__(256) void conv_b() {
    __shared__ float s[64][17];       // s[kk][n]
    int np = blockIdx.x;              // 0..63
    int n0 = np * 16;
    int t = threadIdx.x;
    float4* Bg = (float4*)g_Bt;
    const float* Br = (const float*)g_UT;

    for (int k0 = 0; k0 < DIM; k0 += 64) {
#pragma unroll
        for (int p = 0; p < 4; p++) {
            int li = t + 256 * p;
            int kk = li >> 4, n = li & 15;
            s[kk][n] = Br[(size_t)(k0 + kk) * 1024 + n0 + n];
        }
        __syncthreads();
        {
            int ksl = t >> 5, lane = t & 31;
            int r = lane >> 2, cg = lane & 3;
            int c = ksl * 8 + cg;
            float4 v;
            v.x = __uint_as_float(f2tf32(s[c][r]));
            v.y = __uint_as_float(f2tf32(s[c + 4][r]));
            v.z = __uint_as_float(f2tf32(s[c][r + 8]));
            v.w = __uint_as_float(f2tf32(s[c + 4][r + 8]));
            Bg[((size_t)np * 64 + (k0 >> 3) + ksl) * 32 + lane] = v;
        }
        __syncthreads();
    }
}

// ---------------- kernel 2b: X -> fragment-major tf32 ----------------
// Frag float4 at [rb][ks][lane] = {A[rb*16+r][8ks+cg], A[rb*16+8+r][8ks+cg],
//                                  A[rb*16+r][8ks+cg+4], A[rb*16+8+r][8ks+cg+4]}
__global__ __launch_bounds__(256) void conv_x(const float* __restrict__ X) {
    __shared__ float s[16][516];
    int rb = blockIdx.x;              // 0..1023
    int m0 = rb * 16;
    int t = threadIdx.x;
    {
        int row = t >> 4, cb = (t & 15) * 32;
        const float4* src = (const float4*)(X + (size_t)(m0 + row) * DIM + cb);
#pragma unroll
        for (int i = 0; i < 8; i++)
            *(float4*)&s[row][cb + 4 * i] = src[i];
    }
    __syncthreads();
    float4* Ag = (float4*)g_Xt;
#pragma unroll
    for (int i = 0; i < 8; i++) {
        int j = t + 256 * i;
        int ks = j >> 5, lane = j & 31;
        int r = lane >> 2, cg = lane & 3;
        int c = ks * 8 + cg;
        float4 v;
        v.x = __uint_as_float(f2tf32(s[r][c]));
        v.y = __uint_as_float(f2tf32(s[r + 8][c]));
        v.z = __uint_as_float(f2tf32(s[r][c + 4]));
        v.w = __uint_as_float(f2tf32(s[r + 8][c + 4]));
        Ag[((size_t)rb * 64 + ks) * 32 + lane] = v;
    }
}

// ---------------- kernel 3: tf32 HMMA GEMM + fused <Z> epilogue ----------------
// smem (float4 units): stage s at s*2048; A [0,1024), B [1024,2048) within stage.
#define SMEM_BYTES 65536

__global__ __launch_bounds__(256, 2) void gemm_tc() {
    extern __shared__ uint4 sm4[];
    uint32_t sb = smem_u32(sm4);
    int tid = threadIdx.x, wid = tid >> 5, lane = tid & 31;
    int bx = blockIdx.x;              // n tile (8)
    int rbBase = blockIdx.y * 8;      // A 16-row blocks
    int npBase = bx * 8;              // B 16-n blocks
    int m0 = blockIdx.y * BM;

    int mw = (wid & 1) * 64;
    int nw = (wid >> 1) * 32;
    int r  = lane >> 2, cg = lane & 3;
    int aB = (wid & 1) * 4;           // rb_local base
    int pB = (wid >> 1) * 2;          // np_local base

    float acc[4][4][4];
#pragma unroll
    for (int i = 0; i < 4; i++)
#pragma unroll
        for (int j = 0; j < 4; j++)
#pragma unroll
            for (int v = 0; v < 4; v++) acc[i][j][v] = 0.f;

    const float4* Ag = (const float4*)g_Xt;
    const float4* Bg = (const float4*)g_Bt;

    // per-thread load slots: j = tid + 256*s -> rb=(j>>7), ksl=(j>>5)&3, ln=j&31
    int rbL[4], ksL[4], lnL[4];
#pragma unroll
    for (int s = 0; s < 4; s++) {
        int j = tid + 256 * s;
        rbL[s] = j >> 7; ksL[s] = (j >> 5) & 3; lnL[s] = j & 31;
    }

    // prefetch chunk 0
#pragma unroll
    for (int s = 0; s < 4; s++) {
        uint32_t so = (uint32_t)((rbL[s] * 128 + ksL[s] * 32 + lnL[s]) * 16);
        cp16(sb + so,
             &Ag[((size_t)(rbBase + rbL[s]) * 64 + ksL[s]) * 32 + lnL[s]]);
        cp16(sb + 16384u + so,
             &Bg[((size_t)(npBase + rbL[s]) * 64 + ksL[s]) * 32 + lnL[s]]);
    }
    asm volatile("cp.async.commit_group;");

    for (int ki = 0; ki < NCHUNK; ki++) {
        if (ki + 1 < NCHUNK) {
            uint32_t bufo = ((ki + 1) & 1) * 32768u;
#pragma unroll
            for (int s = 0; s < 4; s++) {
                uint32_t so = bufo + (uint32_t)((rbL[s] * 128 + ksL[s] * 32 + lnL[s]) * 16);
                cp16(sb + so,
                     &Ag[((size_t)(rbBase + rbL[s]) * 64 + (ki + 1) * 4 + ksL[s]) * 32 + lnL[s]]);
                cp16(sb + 16384u + so,
                     &Bg[((size_t)(npBase + rbL[s]) * 64 + (ki + 1) * 4 + ksL[s]) * 32 + lnL[s]]);
            }
            asm volatile("cp.async.commit_group;");
            asm volatile("cp.async.wait_group 1;");
        } else {
            asm volatile("cp.async.wait_group 0;");
        }
        __syncthreads();

        const uint4* As4 = sm4 + (ki & 1) * 2048;
        const uint4* Bs4 = As4 + 1024;
#pragma unroll
        for (int ks = 0; ks < 4; ks++) {
            uint4 a4[4], b4[2];
#pragma unroll
            for (int i = 0; i < 4; i++)
                a4[i] = As4[(aB + i) * 128 + ks * 32 + lane];
#pragma unroll
            for (int p = 0; p < 2; p++)
                b4[p] = Bs4[(pB + p) * 128 + ks * 32 + lane];
#pragma unroll
            for (int i = 0; i < 4; i++)
#pragma unroll
                for (int p = 0; p < 2; p++) {
                    mma_tf32(acc[i][2 * p],     a4[i].x, a4[i].y, a4[i].z, a4[i].w,
                             b4[p].x, b4[p].y);
                    mma_tf32(acc[i][2 * p + 1], a4[i].x, a4[i].y, a4[i].z, a4[i].w,
                             b4[p].z, b4[p].w);
                }
        }
        __syncthreads();
    }

    // ---- fused epilogue (unchanged from R8) ----
    float* part = (float*)sm4;        // [128][10]
    for (int t = tid; t < 1280; t += 256) part[t] = 0.f;
    __syncthreads();

#pragma unroll
    for (int i = 0; i < 4; i++) {
#pragma unroll
        for (int v = 0; v < 2; v++) {
            int prow = mw + 16 * i + r + 8 * v;
            float loc[10];
#pragma unroll
            for (int q = 0; q < 10; q++) loc[q] = 0.f;
#pragma unroll
            for (int j = 0; j < 4; j++) {
                float re = acc[i][j][2 * v], im = acc[i][j][2 * v + 1];
                float p = fmaf(re, re, im * im);
                int nc = bx * 64 + ((nw + 8 * j) >> 1) + cg;
                loc[9] += p;
#pragma unroll
                for (int q = 0; q < 9; q++)
                    loc[q] += ((nc >> (8 - q)) & 1) ? -p : p;
            }
#pragma unroll
            for (int o = 1; o < 4; o <<= 1)
#pragma unroll
                for (int q = 0; q < 10; q++)
                    loc[q] += __shfl_xor_sync(0xffffffffu, loc[q], o);
            if (cg == 0)
#pragma unroll
                for (int q = 0; q < 10; q++)
                    atomicAdd(&part[prow * 10 + q], loc[q]);
        }
    }
    __syncthreads();
    if (tid < 128) {
        float* dst = g_part + ((size_t)bx * BATCH + m0 + tid) * 10;
#pragma unroll
        for (int q = 0; q < 10; q++) dst[q] = part[tid * 10 + q];
    }
}

// ---------------- kernel 4: sum partials -> head -> log_softmax ----------------
__global__ __launch_bounds__(256) void head_k(const float* __restrict__ fc_w,
                                              const float* __restrict__ fc_b,
                                              float* __restrict__ out) {
    int row = blockIdx.x * 256 + threadIdx.x;
    float a[10];
#pragma unroll
    for (int q = 0; q < 10; q++) a[q] = 0.f;
#pragma unroll
    for (int b = 0; b < 8; b++) {
        const float* p = g_part + ((size_t)b * BATCH + row) * 10;
#pragma unroll
        for (int q = 0; q < 10; q++) a[q] += p[q];
    }
    float inv = 1.0f / a[9];
    float z[9];
#pragma unroll
    for (int q = 0; q < 9; q++) z[q] = a[q] * inv;
    float lg[NCLS]; float mx = -1e30f;
#pragma unroll
    for (int c = 0; c < NCLS; c++) {
        float s = fc_b[c];
#pragma unroll
        for (int q = 0; q < 9; q++) s = fmaf(fc_w[c * 9 + q], z[q], s);
        lg[c] = s; mx = fmaxf(mx, s);
    }
    float se = 0.f;
#pragma unroll
    for (int c = 0; c < NCLS; c++) se += expf(lg[c] - mx);
    float lse = mx + logf(se);
    float* o10 = out + (size_t)row * NCLS;
#pragma unroll
    for (int c = 0; c < NCLS; c++) o10[c] = lg[c] - lse;
}

// ---------------- launch ----------------
extern "C" void kernel_launch(void* const* d_in, const int* in_sizes, int n_in,
                              void* d_out, int out_size) {
    const float* x    = (const float*)d_in[0];
    const float* rot  = (const float*)d_in[1];
    const float* crx  = (const float*)d_in[2];
    const float* fc_w = (const float*)d_in[3];
    const float* fc_b = (const float*)d_in[4];
    float* out = (float*)d_out;

    static bool attr_set = false;
    if (!attr_set) {
        cudaFuncSetAttribute(gemm_tc, cudaFuncAttributeMaxDynamicSharedMemorySize,
                             SMEM_BYTES);
        attr_set = true;
    }

    gate_prep<<<1, 128>>>(rot, crx);
    build_u<<<DIM, 256>>>();
    conv_b<<<64, 256>>>();
    conv_x<<<BATCH / 16, 256>>>(x);
    gemm_tc<<<dim3(1024 / BN, BATCH / BM), 256, SMEM_BYTES>>>();
    head_k<<<BATCH / 256, 256>>>(fc_w, fc_b, out);
    (void)in_sizes; (void)n_in; (void)out_size;
}